// round 1
// baseline (speedup 1.0000x reference)
#include <cuda_runtime.h>
#include <math.h>

// Problem constants
#define NTOK   32768      // B*H*W = 32*32*32
#define KCB    1024       // codebook entries
#define DIM    64         // embedding dim
#define HWSZ   1024       // H*W
#define QELEMS 2097152    // NTOK*DIM
#define EPSF   0.05f
#define NSTEPS 10

// ---------------- scratch (device globals; no allocations) ----------------
__device__ float g_csq[KCB];
__device__ float g_tgt[KCB];
__device__ float g_logtgt[KCB];
__device__ int   g_hist[KCB];
__device__ float g_src[KCB];
__device__ float g_phi[KCB];
__device__ float g_lse[KCB];
__device__ float g_msepart[256];
__device__ float g_mse;

// ---------------- K0: init (zero state, |c|^2, gaussian target) ------------
__global__ void k_init(const float* __restrict__ cb) {
    int j = threadIdx.x;               // 1024 threads
    g_hist[j] = 0;
    g_phi[j]  = 0.0f;

    float s = 0.0f;
    #pragma unroll
    for (int k = 0; k < DIM; k++) { float c = cb[j * DIM + k]; s = fmaf(c, c, s); }
    g_csq[j] = s;

    // gaussian target, normalized twice (faithful to _gaussian_target + _norm_prob)
    float z = ((float)j - 511.5f) / (1024.0f / 6.0f);
    float t = expf(-0.5f * z * z);

    __shared__ float sh[KCB];
    sh[j] = t; __syncthreads();
    for (int o = 512; o > 0; o >>= 1) { if (j < o) sh[j] += sh[j + o]; __syncthreads(); }
    float sum1 = sh[0]; __syncthreads();

    float t1 = t / fmaxf(sum1, 1e-12f);
    float t2 = fmaxf(t1, 1e-12f);
    sh[j] = t2; __syncthreads();
    for (int o = 512; o > 0; o >>= 1) { if (j < o) sh[j] += sh[j + o]; __syncthreads(); }
    float sum2 = sh[0];

    float tg = t2 / sum2;
    g_tgt[j]    = tg;
    g_logtgt[j] = logf(fmaxf(tg, 1e-12f));
}

// ---------------- K1: distances + argmin + hist + mse + quantized ----------
__global__ void __launch_bounds__(128) k_main(const float* __restrict__ x,
                                              const float* __restrict__ cb,
                                              float* __restrict__ out) {
    const int tid = threadIdx.x;
    const int n   = blockIdx.x * 128 + tid;      // token id (block stays within one batch b)
    const int b   = n >> 10;
    const int hw  = n & 1023;

    const float* xb = x + (size_t)b * (DIM * HWSZ) + hw;
    float xr[DIM];
    #pragma unroll
    for (int k = 0; k < DIM; k++) xr[k] = xb[k * HWSZ];

    float xsq = 0.0f;
    #pragma unroll
    for (int k = 0; k < DIM; k++) xsq = fmaf(xr[k], xr[k], xsq);

    __shared__ float s_code[128 * DIM];   // 32 KB chunk of codebook
    __shared__ float s_csq[128];
    __shared__ int   s_hist[KCB];
    #pragma unroll
    for (int k = 0; k < 8; k++) s_hist[tid + 128 * k] = 0;

    float best  = 3.4e38f;
    int   bestj = 0;

    for (int c0 = 0; c0 < KCB; c0 += 128) {
        __syncthreads();
        const float4* src4 = (const float4*)(cb + (size_t)c0 * DIM);
        float4* dst4 = (float4*)s_code;
        #pragma unroll
        for (int t = 0; t < 16; t++) dst4[tid + 128 * t] = src4[tid + 128 * t];
        s_csq[tid] = g_csq[c0 + tid];
        __syncthreads();

        for (int j = 0; j < 128; j++) {
            const float4* cp = (const float4*)(s_code + j * DIM);
            float a0 = 0.f, a1 = 0.f, a2 = 0.f, a3 = 0.f;
            #pragma unroll
            for (int t = 0; t < 16; t++) {
                float4 c4 = cp[t];
                a0 = fmaf(xr[4 * t + 0], c4.x, a0);
                a1 = fmaf(xr[4 * t + 1], c4.y, a1);
                a2 = fmaf(xr[4 * t + 2], c4.z, a2);
                a3 = fmaf(xr[4 * t + 3], c4.w, a3);
            }
            float dot = (a0 + a1) + (a2 + a3);
            // faithful to reference op structure: (|x|^2 + |c|^2) - 2*dot (no FMA contraction)
            float d = __fsub_rn(__fadd_rn(xsq, s_csq[j]), __fmul_rn(2.0f, dot));
            if (d < best) { best = d; bestj = c0 + j; }   // strict < = first-min (argmin semantics)
        }
    }

    // block histogram -> global (integer atomics: deterministic)
    atomicAdd(&s_hist[bestj], 1);
    __syncthreads();
    #pragma unroll
    for (int k = 0; k < 8; k++) {
        int v = s_hist[tid + 128 * k];
        if (v) atomicAdd(&g_hist[tid + 128 * k], v);
    }

    // quantized output (straight-through value: x + (q - x)) + mse partial
    const float* q = cb + (size_t)bestj * DIM;
    float* ob = out + (size_t)b * (DIM * HWSZ) + hw;
    float ms = 0.0f;
    #pragma unroll
    for (int k = 0; k < DIM; k++) {
        float qv = __ldg(q + k);
        float dv = __fsub_rn(qv, xr[k]);
        ms = fmaf(dv, dv, ms);
        ob[k * HWSZ] = __fadd_rn(xr[k], dv);
    }
    // deterministic per-block mse reduce
    for (int o = 16; o > 0; o >>= 1) ms += __shfl_xor_sync(0xffffffffu, ms, o);
    __shared__ float s_ms[4];
    if ((tid & 31) == 0) s_ms[tid >> 5] = ms;
    __syncthreads();
    if (tid == 0) g_msepart[blockIdx.x] = (s_ms[0] + s_ms[1]) + (s_ms[2] + s_ms[3]);
}

// ---------------- K2: perplexity, src weights, total mse --------------------
__global__ void k_stats(float* __restrict__ out) {
    int j = threadIdx.x;               // 1024 threads
    __shared__ float sh[KCB];

    float avg = (float)g_hist[j] / (float)NTOK;

    // perplexity = exp(-sum(avg*log(avg+1e-10)))
    float ent = avg * logf(avg + 1e-10f);
    sh[j] = ent; __syncthreads();
    for (int o = 512; o > 0; o >>= 1) { if (j < o) sh[j] += sh[j + o]; __syncthreads(); }
    if (j == 0) out[QELEMS + 1] = expf(-sh[0]);
    __syncthreads();

    // cw = norm_prob(hard_hist), then norm_prob again inside _dual_obj
    float p1 = fmaxf(avg, 1e-12f);
    sh[j] = p1; __syncthreads();
    for (int o = 512; o > 0; o >>= 1) { if (j < o) sh[j] += sh[j + o]; __syncthreads(); }
    float s1 = sh[0]; __syncthreads();
    float cw = p1 / s1;
    float p2 = fmaxf(cw, 1e-12f);
    sh[j] = p2; __syncthreads();
    for (int o = 512; o > 0; o >>= 1) { if (j < o) sh[j] += sh[j + o]; __syncthreads(); }
    float s2 = sh[0]; __syncthreads();
    g_src[j] = p2 / s2;

    // total mse from 256 deterministic partials
    sh[j] = (j < 256) ? g_msepart[j] : 0.0f;
    __syncthreads();
    for (int o = 512; o > 0; o >>= 1) { if (j < o) sh[j] += sh[j + o]; __syncthreads(); }
    if (j == 0) g_mse = sh[0];
}

// ---------------- K3: row logsumexp over j (one block per i) ----------------
__global__ void __launch_bounds__(256) k_lse() {
    int i = blockIdx.x;
    int t = threadIdx.x;
    float fi = (float)i;

    float a[4];
    #pragma unroll
    for (int u = 0; u < 4; u++) {
        int j = t + 256 * u;
        a[u] = g_logtgt[j] + (g_phi[j] - fabsf(fi - (float)j)) / EPSF;
    }
    __shared__ float sh[256];
    float m4 = fmaxf(fmaxf(a[0], a[1]), fmaxf(a[2], a[3]));
    sh[t] = m4; __syncthreads();
    for (int o = 128; o > 0; o >>= 1) { if (t < o) sh[t] = fmaxf(sh[t], sh[t + o]); __syncthreads(); }
    float m = sh[0]; __syncthreads();

    float s4 = expf(a[0] - m) + expf(a[1] - m) + expf(a[2] - m) + expf(a[3] - m);
    sh[t] = s4; __syncthreads();
    for (int o = 128; o > 0; o >>= 1) { if (t < o) sh[t] += sh[t + o]; __syncthreads(); }
    if (t == 0) g_lse[i] = m + logf(sh[0]);
}

// ---------------- K4: marginal over i + phi update (one block per j) --------
__global__ void __launch_bounds__(256) k_upd() {
    int j = blockIdx.x;
    int t = threadIdx.x;
    float phj  = g_phi[j];
    float base = g_logtgt[j];
    float fj   = (float)j;

    float s = 0.0f;
    #pragma unroll
    for (int u = 0; u < 4; u++) {
        int i = t + 256 * u;
        float a = base + (phj - fabsf((float)i - fj)) / EPSF;
        s += g_src[i] * expf(a - g_lse[i]);
    }
    __shared__ float sh[256];
    sh[t] = s; __syncthreads();
    for (int o = 128; o > 0; o >>= 1) { if (t < o) sh[t] += sh[t + o]; __syncthreads(); }
    if (t == 0) g_phi[j] = phj + 0.5f * (g_tgt[j] - sh[0]);
}

// ---------------- K5: final dual objective + loss ---------------------------
__global__ void k_final(float* __restrict__ out) {
    int j = threadIdx.x;               // 1024 threads
    __shared__ float sh[KCB];

    float v1 = g_src[j] * (-EPSF * g_lse[j]);
    sh[j] = v1; __syncthreads();
    for (int o = 512; o > 0; o >>= 1) { if (j < o) sh[j] += sh[j + o]; __syncthreads(); }
    float s1 = sh[0]; __syncthreads();

    float v2 = g_tgt[j] * g_phi[j];
    sh[j] = v2; __syncthreads();
    for (int o = 512; o > 0; o >>= 1) { if (j < o) sh[j] += sh[j + o]; __syncthreads(); }
    float s2 = sh[0];

    if (j == 0) {
        float obj = s1 + s2;                         // ot_loss (OT_W = 1)
        float m = g_mse / (float)QELEMS;             // codebook_loss == commit_loss value
        out[QELEMS] = (m + 0.25f * m) + obj;         // loss
    }
}

// ---------------- launch ----------------------------------------------------
extern "C" void kernel_launch(void* const* d_in, const int* in_sizes, int n_in,
                              void* d_out, int out_size) {
    const float* x  = (const float*)d_in[0];   // inputs [32,64,32,32]
    const float* cb = (const float*)d_in[1];   // codebook [1024,64]
    if (n_in >= 2 && in_sizes[0] == KCB * DIM && in_sizes[1] == QELEMS) {
        // defensive: swap if metadata order differs
        x = (const float*)d_in[1]; cb = (const float*)d_in[0];
    }
    float* out = (float*)d_out;

    k_init<<<1, 1024>>>(cb);
    k_main<<<NTOK / 128, 128>>>(x, cb, out);
    k_stats<<<1, 1024>>>(out);
    for (int s = 0; s < NSTEPS; s++) {
        k_lse<<<KCB, 256>>>();
        k_upd<<<KCB, 256>>>();
    }
    k_lse<<<KCB, 256>>>();
    k_final<<<1, 1024>>>(out);
}

// round 2
// speedup vs baseline: 1.0394x; 1.0394x over previous
#include <cuda_runtime.h>
#include <math.h>

// Problem constants
#define NTOK   32768      // B*H*W = 32*32*32
#define KCB    1024       // codebook entries
#define DIM    64         // embedding dim
#define HWSZ   1024       // H*W
#define QELEMS 2097152    // NTOK*DIM
#define EPSF   0.05f
#define NSTEPS 10
#define WIN    5          // OT stencil half-width (e^-100 tail, below fp32 ulp)

// ---------------- scratch (device globals; no allocations) ----------------
__device__ float g_csq[KCB];
__device__ float g_tgt[KCB];
__device__ float g_logtgt[KCB];
__device__ int   g_hist[KCB];
__device__ float g_msepart[256];

// ---------------- K0: init (zero hist, |c|^2, gaussian target) -------------
__global__ void k_init(const float* __restrict__ cb) {
    int j = threadIdx.x;               // 1024 threads
    g_hist[j] = 0;

    float s = 0.0f;
    #pragma unroll
    for (int k = 0; k < DIM; k++) { float c = cb[j * DIM + k]; s = fmaf(c, c, s); }
    g_csq[j] = s;

    // gaussian target, normalized twice (faithful to _gaussian_target + _norm_prob)
    float z = ((float)j - 511.5f) / (1024.0f / 6.0f);
    float t = expf(-0.5f * z * z);

    __shared__ float sh[KCB];
    sh[j] = t; __syncthreads();
    for (int o = 512; o > 0; o >>= 1) { if (j < o) sh[j] += sh[j + o]; __syncthreads(); }
    float sum1 = sh[0]; __syncthreads();

    float t1 = t / fmaxf(sum1, 1e-12f);
    float t2 = fmaxf(t1, 1e-12f);
    sh[j] = t2; __syncthreads();
    for (int o = 512; o > 0; o >>= 1) { if (j < o) sh[j] += sh[j + o]; __syncthreads(); }
    float sum2 = sh[0];

    float tg = t2 / sum2;
    g_tgt[j]    = tg;
    g_logtgt[j] = logf(fmaxf(tg, 1e-12f));
}

// ---------------- K1: distances + argmin + hist + mse + quantized ----------
// Packed f32x2 FMA: two fp32 MACs per issue slot, rounding identical to scalar.
__global__ void __launch_bounds__(128) k_main(const float* __restrict__ x,
                                              const float* __restrict__ cb,
                                              float* __restrict__ out) {
    const int tid = threadIdx.x;
    const int n   = blockIdx.x * 128 + tid;      // token id (block stays within one batch b)
    const int b   = n >> 10;
    const int hw  = n & 1023;

    const float* xb = x + (size_t)b * (DIM * HWSZ) + hw;
    float xr[DIM];
    #pragma unroll
    for (int k = 0; k < DIM; k++) xr[k] = xb[k * HWSZ];

    float xsq = 0.0f;
    #pragma unroll
    for (int k = 0; k < DIM; k++) xsq = fmaf(xr[k], xr[k], xsq);

    // pack x into f32x2 pairs (smem codebook floats are already pair-layout)
    unsigned long long xp[32];
    #pragma unroll
    for (int t = 0; t < 32; t++)
        asm("mov.b64 %0, {%1, %2};" : "=l"(xp[t]) : "f"(xr[2 * t]), "f"(xr[2 * t + 1]));

    __shared__ float s_code[128 * DIM];   // 32 KB chunk of codebook
    __shared__ float s_csq[128];
    __shared__ int   s_hist[KCB];
    #pragma unroll
    for (int k = 0; k < 8; k++) s_hist[tid + 128 * k] = 0;

    float best  = 3.4e38f;
    int   bestj = 0;

    for (int c0 = 0; c0 < KCB; c0 += 128) {
        __syncthreads();
        const float4* src4 = (const float4*)(cb + (size_t)c0 * DIM);
        float4* dst4 = (float4*)s_code;
        #pragma unroll
        for (int t = 0; t < 16; t++) dst4[tid + 128 * t] = src4[tid + 128 * t];
        s_csq[tid] = g_csq[c0 + tid];
        __syncthreads();

        for (int j = 0; j < 128; j++) {
            const ulonglong2* cp = (const ulonglong2*)(s_code + j * DIM);
            unsigned long long a0 = 0ull, a1 = 0ull, a2 = 0ull, a3 = 0ull;
            #pragma unroll
            for (int t = 0; t < 16; t += 2) {
                ulonglong2 cA = cp[t];
                ulonglong2 cB = cp[t + 1];
                asm("fma.rn.f32x2 %0, %1, %2, %0;" : "+l"(a0) : "l"(xp[2 * t + 0]), "l"(cA.x));
                asm("fma.rn.f32x2 %0, %1, %2, %0;" : "+l"(a1) : "l"(xp[2 * t + 1]), "l"(cA.y));
                asm("fma.rn.f32x2 %0, %1, %2, %0;" : "+l"(a2) : "l"(xp[2 * t + 2]), "l"(cB.x));
                asm("fma.rn.f32x2 %0, %1, %2, %0;" : "+l"(a3) : "l"(xp[2 * t + 3]), "l"(cB.y));
            }
            float l0, h0, l1, h1, l2, h2, l3, h3;
            asm("mov.b64 {%0, %1}, %2;" : "=f"(l0), "=f"(h0) : "l"(a0));
            asm("mov.b64 {%0, %1}, %2;" : "=f"(l1), "=f"(h1) : "l"(a1));
            asm("mov.b64 {%0, %1}, %2;" : "=f"(l2), "=f"(h2) : "l"(a2));
            asm("mov.b64 {%0, %1}, %2;" : "=f"(l3), "=f"(h3) : "l"(a3));
            float dot = ((l0 + h0) + (l1 + h1)) + ((l2 + h2) + (l3 + h3));
            // faithful op structure: (|x|^2 + |c|^2) - 2*dot (no FMA contraction)
            float d = __fsub_rn(__fadd_rn(xsq, s_csq[j]), __fmul_rn(2.0f, dot));
            if (d < best) { best = d; bestj = c0 + j; }   // strict < = first-min
        }
    }

    // block histogram -> global (integer atomics: deterministic)
    atomicAdd(&s_hist[bestj], 1);
    __syncthreads();
    #pragma unroll
    for (int k = 0; k < 8; k++) {
        int v = s_hist[tid + 128 * k];
        if (v) atomicAdd(&g_hist[tid + 128 * k], v);
    }

    // quantized output (straight-through value: x + (q - x)) + mse partial
    const float* q = cb + (size_t)bestj * DIM;
    float* ob = out + (size_t)b * (DIM * HWSZ) + hw;
    float ms = 0.0f;
    #pragma unroll
    for (int k = 0; k < DIM; k++) {
        float qv = __ldg(q + k);
        float dv = __fsub_rn(qv, xr[k]);
        ms = fmaf(dv, dv, ms);
        ob[k * HWSZ] = __fadd_rn(xr[k], dv);
    }
    // deterministic per-block mse reduce
    for (int o = 16; o > 0; o >>= 1) ms += __shfl_xor_sync(0xffffffffu, ms, o);
    __shared__ float s_ms[4];
    if ((tid & 31) == 0) s_ms[tid >> 5] = ms;
    __syncthreads();
    if (tid == 0) g_msepart[blockIdx.x] = (s_ms[0] + s_ms[1]) + (s_ms[2] + s_ms[3]);
}

// ---------------- K2: stats + full OT dual loop + loss (one CTA) ------------
// eps=0.05 => each unit |i-j| costs e^-20 in the Gibbs kernel while
// u_j = log t_j + phi_j/eps drifts by ~0.02/unit. Terms beyond |i-j|=WIN are
// < e^-(20*WIN-2) relative — below fp32 ulp, so a +/-WIN stencil is exact.
__global__ void __launch_bounds__(1024) k_ot(float* __restrict__ out) {
    const int j = threadIdx.x;               // 1024 threads, thread j owns index j
    __shared__ float sh[KCB];
    __shared__ float s_lt[KCB];
    __shared__ float s_phi[KCB];
    __shared__ float s_lse[KCB];
    __shared__ float s_src[KCB];

    const float tgt = g_tgt[j];
    const float lt  = g_logtgt[j];
    s_lt[j] = lt;

    // ---- perplexity ----
    float avg = (float)g_hist[j] / (float)NTOK;
    sh[j] = avg * logf(avg + 1e-10f); __syncthreads();
    for (int o = 512; o > 0; o >>= 1) { if (j < o) sh[j] += sh[j + o]; __syncthreads(); }
    if (j == 0) out[QELEMS + 1] = expf(-sh[0]);
    __syncthreads();

    // ---- src weights: norm_prob(hard_hist) then norm_prob again (dual_obj) ----
    float p1 = fmaxf(avg, 1e-12f);
    sh[j] = p1; __syncthreads();
    for (int o = 512; o > 0; o >>= 1) { if (j < o) sh[j] += sh[j + o]; __syncthreads(); }
    float s1 = sh[0]; __syncthreads();
    float p2 = fmaxf(p1 / s1, 1e-12f);
    sh[j] = p2; __syncthreads();
    for (int o = 512; o > 0; o >>= 1) { if (j < o) sh[j] += sh[j + o]; __syncthreads(); }
    float s2 = sh[0]; __syncthreads();
    const float src = p2 / s2;
    s_src[j] = src;

    // ---- total mse ----
    sh[j] = (j < 256) ? g_msepart[j] : 0.0f; __syncthreads();
    for (int o = 512; o > 0; o >>= 1) { if (j < o) sh[j] += sh[j + o]; __syncthreads(); }
    const float mse_tot = sh[0];

    // ---- dual ascent loop ----
    float phi = 0.0f;
    s_phi[j] = 0.0f;
    const int lo = (j - WIN < 0) ? 0 : j - WIN;
    const int hi = (j + WIN > KCB - 1) ? KCB - 1 : j + WIN;
    const float fj = (float)j;

    for (int step = 0; step < NSTEPS; step++) {
        __syncthreads();
        // lse_i for i = j (windowed)
        float m = -3.4e38f;
        float a[2 * WIN + 1];
        for (int jj = lo; jj <= hi; jj++) {
            float v = s_lt[jj] + (s_phi[jj] - fabsf(fj - (float)jj)) / EPSF;
            a[jj - lo] = v;
            m = fmaxf(m, v);
        }
        float s = 0.0f;
        for (int jj = lo; jj <= hi; jj++) s += expf(a[jj - lo] - m);
        s_lse[j] = m + logf(s);
        __syncthreads();
        // marginal_j = sum_i src_i * exp(a_ij - lse_i)  (windowed over i)
        float mar = 0.0f;
        for (int i = lo; i <= hi; i++) {
            float v = lt + (phi - fabsf((float)i - fj)) / EPSF;
            mar += s_src[i] * expf(v - s_lse[i]);
        }
        phi = phi + 0.5f * (tgt - mar);
        __syncthreads();
        s_phi[j] = phi;
    }
    __syncthreads();

    // ---- final lse with converged phi ----
    {
        float m = -3.4e38f;
        float a[2 * WIN + 1];
        for (int jj = lo; jj <= hi; jj++) {
            float v = s_lt[jj] + (s_phi[jj] - fabsf(fj - (float)jj)) / EPSF;
            a[jj - lo] = v;
            m = fmaxf(m, v);
        }
        float s = 0.0f;
        for (int jj = lo; jj <= hi; jj++) s += expf(a[jj - lo] - m);
        s_lse[j] = m + logf(s);
    }
    __syncthreads();

    // ---- dual objective + loss ----
    sh[j] = src * (-EPSF * s_lse[j]); __syncthreads();
    for (int o = 512; o > 0; o >>= 1) { if (j < o) sh[j] += sh[j + o]; __syncthreads(); }
    float t1s = sh[0]; __syncthreads();
    sh[j] = tgt * phi; __syncthreads();
    for (int o = 512; o > 0; o >>= 1) { if (j < o) sh[j] += sh[j + o]; __syncthreads(); }
    float t2s = sh[0];

    if (j == 0) {
        float obj = t1s + t2s;                        // ot_loss (OT_W = 1)
        float m = mse_tot / (float)QELEMS;            // codebook_loss == commit_loss value
        out[QELEMS] = (m + 0.25f * m) + obj;          // loss
    }
}

// ---------------- launch ----------------------------------------------------
extern "C" void kernel_launch(void* const* d_in, const int* in_sizes, int n_in,
                              void* d_out, int out_size) {
    const float* x  = (const float*)d_in[0];   // inputs [32,64,32,32]
    const float* cb = (const float*)d_in[1];   // codebook [1024,64]
    if (n_in >= 2 && in_sizes[0] == KCB * DIM && in_sizes[1] == QELEMS) {
        x = (const float*)d_in[1]; cb = (const float*)d_in[0];
    }
    float* out = (float*)d_out;

    k_init<<<1, 1024>>>(cb);
    k_main<<<NTOK / 128, 128>>>(x, cb, out);
    k_ot<<<1, 1024>>>(out);
}

// round 4
// speedup vs baseline: 1.5016x; 1.4447x over previous
#include <cuda_runtime.h>
#include <math.h>

// Problem constants
#define NTOK   32768      // B*H*W = 32*32*32
#define KCB    1024       // codebook entries
#define DIM    64         // embedding dim
#define HWSZ   1024       // H*W
#define QELEMS 2097152    // NTOK*DIM
#define INVEPS 20.0f      // 1/0.05 (exact within <1 ulp of f32 division by 0.05f)
#define NSTEPS 10
#define WIN    3          // OT stencil half-width; tail < e^-60, below fp32 ulp
                          // (validated R2: WIN=5 rel_err identical to exact OT)

// ---------------- scratch (device globals; no allocations) ----------------
__device__ float g_csq[KCB];
__device__ int   g_hist[KCB];
__device__ float g_msepart[256];

// ---------------- K0: |c|^2 + hist zero (parallel, trivial) ----------------
__global__ void k_sq(const float* __restrict__ cb) {
    int j = blockIdx.x * 128 + threadIdx.x;      // grid 8 x 128 = 1024
    const float4* r = (const float4*)(cb + (size_t)j * DIM);
    float s = 0.0f;
    #pragma unroll
    for (int t = 0; t < 16; t++) {
        float4 c = __ldg(r + t);
        s = fmaf(c.x, c.x, s); s = fmaf(c.y, c.y, s);
        s = fmaf(c.z, c.z, s); s = fmaf(c.w, c.w, s);
    }
    g_csq[j]  = s;
    g_hist[j] = 0;
}

// ---------------- K1: distances + argmin + hist + mse + quantized ----------
// x kept ONLY in packed f32x2 form (64 regs); unpacked at epilogue via
// register-pair aliasing. fma.rn.f32x2 = 2 fp32 MACs / issue slot.
__global__ void __launch_bounds__(128) k_main(const float* __restrict__ x,
                                              const float* __restrict__ cb,
                                              float* __restrict__ out) {
    const int tid = threadIdx.x;
    const int n   = blockIdx.x * 128 + tid;      // block stays within one batch b
    const int b   = n >> 10;
    const int hw  = n & 1023;

    const float* xb = x + (size_t)b * (DIM * HWSZ) + hw;
    unsigned long long xp[32];
    float xsq = 0.0f;
    #pragma unroll
    for (int t = 0; t < 32; t++) {
        float e0 = xb[(2 * t) * HWSZ];
        float e1 = xb[(2 * t + 1) * HWSZ];
        xsq = fmaf(e0, e0, xsq);
        xsq = fmaf(e1, e1, xsq);
        asm("mov.b64 %0, {%1, %2};" : "=l"(xp[t]) : "f"(e0), "f"(e1));
    }

    __shared__ float s_code[128 * DIM];   // 32 KB chunk of codebook
    __shared__ float s_csq[128];
    __shared__ int   s_hist[KCB];
    #pragma unroll
    for (int k = 0; k < 8; k++) s_hist[tid + 128 * k] = 0;

    float best  = 3.4e38f;
    int   bestj = 0;

    for (int c0 = 0; c0 < KCB; c0 += 128) {
        __syncthreads();
        const float4* src4 = (const float4*)(cb + (size_t)c0 * DIM);
        float4* dst4 = (float4*)s_code;
        #pragma unroll
        for (int t = 0; t < 16; t++) dst4[tid + 128 * t] = __ldg(src4 + tid + 128 * t);
        s_csq[tid] = g_csq[c0 + tid];
        __syncthreads();

        #pragma unroll 2
        for (int j = 0; j < 128; j++) {
            const ulonglong2* cp = (const ulonglong2*)(s_code + j * DIM);
            unsigned long long a0 = 0ull, a1 = 0ull, a2 = 0ull, a3 = 0ull;
            #pragma unroll
            for (int t = 0; t < 16; t += 2) {
                ulonglong2 cA = cp[t];
                ulonglong2 cB = cp[t + 1];
                asm("fma.rn.f32x2 %0, %1, %2, %0;" : "+l"(a0) : "l"(xp[2 * t + 0]), "l"(cA.x));
                asm("fma.rn.f32x2 %0, %1, %2, %0;" : "+l"(a1) : "l"(xp[2 * t + 1]), "l"(cA.y));
                asm("fma.rn.f32x2 %0, %1, %2, %0;" : "+l"(a2) : "l"(xp[2 * t + 2]), "l"(cB.x));
                asm("fma.rn.f32x2 %0, %1, %2, %0;" : "+l"(a3) : "l"(xp[2 * t + 3]), "l"(cB.y));
            }
            // packed tree combine (3 ADD2 + 1 scalar add)
            unsigned long long c01, c23, cc;
            asm("add.rn.f32x2 %0, %1, %2;" : "=l"(c01) : "l"(a0), "l"(a1));
            asm("add.rn.f32x2 %0, %1, %2;" : "=l"(c23) : "l"(a2), "l"(a3));
            asm("add.rn.f32x2 %0, %1, %2;" : "=l"(cc)  : "l"(c01), "l"(c23));
            float lo, hi;
            asm("mov.b64 {%0, %1}, %2;" : "=f"(lo), "=f"(hi) : "l"(cc));
            float dot = lo + hi;
            // faithful op structure: (|x|^2 + |c|^2) - 2*dot (no FMA contraction)
            float d = __fsub_rn(__fadd_rn(xsq, s_csq[j]), __fmul_rn(2.0f, dot));
            if (d < best) { best = d; bestj = c0 + j; }   // strict < = first-min
        }
    }

    // block histogram -> global (integer atomics: deterministic)
    atomicAdd(&s_hist[bestj], 1);
    __syncthreads();
    #pragma unroll
    for (int k = 0; k < 8; k++) {
        int v = s_hist[tid + 128 * k];
        if (v) atomicAdd(&g_hist[tid + 128 * k], v);
    }

    // quantized output (straight-through value: x + (q - x)) + mse partial
    const float4* q4 = (const float4*)(cb + (size_t)bestj * DIM);
    float* ob = out + (size_t)b * (DIM * HWSZ) + hw;
    float ms = 0.0f;
    #pragma unroll
    for (int t = 0; t < 16; t++) {
        float4 qv = __ldg(q4 + t);
        float x0, x1, x2, x3;
        asm("mov.b64 {%0, %1}, %2;" : "=f"(x0), "=f"(x1) : "l"(xp[2 * t]));
        asm("mov.b64 {%0, %1}, %2;" : "=f"(x2), "=f"(x3) : "l"(xp[2 * t + 1]));
        float d0 = __fsub_rn(qv.x, x0), d1 = __fsub_rn(qv.y, x1);
        float d2 = __fsub_rn(qv.z, x2), d3 = __fsub_rn(qv.w, x3);
        ms = fmaf(d0, d0, ms); ms = fmaf(d1, d1, ms);
        ms = fmaf(d2, d2, ms); ms = fmaf(d3, d3, ms);
        ob[(4 * t + 0) * HWSZ] = __fadd_rn(x0, d0);
        ob[(4 * t + 1) * HWSZ] = __fadd_rn(x1, d1);
        ob[(4 * t + 2) * HWSZ] = __fadd_rn(x2, d2);
        ob[(4 * t + 3) * HWSZ] = __fadd_rn(x3, d3);
    }
    // deterministic per-block mse reduce
    #pragma unroll
    for (int o = 16; o > 0; o >>= 1) ms += __shfl_xor_sync(0xffffffffu, ms, o);
    __shared__ float s_ms[4];
    if ((tid & 31) == 0) s_ms[tid >> 5] = ms;
    __syncthreads();
    if (tid == 0) g_msepart[blockIdx.x] = (s_ms[0] + s_ms[1]) + (s_ms[2] + s_ms[3]);
}

// ---------------- block-wide sum (1024 threads, shuffle + 32 partials) ------
__device__ __forceinline__ float bsum(float v, float* sh32, int tid) {
    #pragma unroll
    for (int o = 16; o > 0; o >>= 1) v += __shfl_xor_sync(0xffffffffu, v, o);
    if ((tid & 31) == 0) sh32[tid >> 5] = v;
    __syncthreads();
    if (tid < 32) {
        float w = sh32[tid];
        #pragma unroll
        for (int o = 16; o > 0; o >>= 1) w += __shfl_xor_sync(0xffffffffu, w, o);
        if (tid == 0) sh32[0] = w;
    }
    __syncthreads();
    float r = sh32[0];
    __syncthreads();
    return r;
}

// ---------------- K2: target + stats + OT dual loop + loss (one CTA) --------
__global__ void __launch_bounds__(1024) k_ot(float* __restrict__ out) {
    const int j = threadIdx.x;               // thread j owns index j
    __shared__ float sh32[32];
    __shared__ float s_lt[KCB];
    __shared__ float s_phi[KCB];
    __shared__ float s_lse[KCB];
    __shared__ float s_src[KCB];

    // ---- gaussian target (faithful: _gaussian_target then _norm_prob) ----
    float z = ((float)j - 511.5f) / (1024.0f / 6.0f);
    float t = expf(-0.5f * z * z);
    float sum1 = bsum(t, sh32, j);
    float t1 = t / fmaxf(sum1, 1e-12f);
    float t2 = fmaxf(t1, 1e-12f);
    float sum2 = bsum(t2, sh32, j);
    const float tgt = t2 / sum2;
    const float lt  = logf(fmaxf(tgt, 1e-12f));
    s_lt[j] = lt;

    // ---- perplexity ----
    float avg = (float)g_hist[j] / (float)NTOK;
    float ent = bsum(avg * logf(avg + 1e-10f), sh32, j);
    if (j == 0) out[QELEMS + 1] = expf(-ent);

    // ---- src weights: norm_prob(hard_hist) then norm_prob again (dual_obj) ----
    float p1 = fmaxf(avg, 1e-12f);
    float s1 = bsum(p1, sh32, j);
    float p2 = fmaxf(p1 / s1, 1e-12f);
    float s2 = bsum(p2, sh32, j);
    const float src = p2 / s2;
    s_src[j] = src;

    // ---- total mse ----
    const float mse_tot = bsum((j < 256) ? g_msepart[j] : 0.0f, sh32, j);

    // ---- dual ascent loop (compile-time +/-WIN stencil, fully unrolled) ----
    float phi = 0.0f;
    s_phi[j] = 0.0f;
    __syncthreads();

    float lse = 0.0f;
    for (int step = 0; step <= NSTEPS; step++) {
        // lse_i for i=j over window
        float a[2 * WIN + 1];
        float m = -3.4e38f;
        #pragma unroll
        for (int u = -WIN; u <= WIN; u++) {
            int jj = j + u;
            bool valid = (jj >= 0) && (jj < KCB);
            int jc = valid ? jj : j;
            float v = s_lt[jc] + fmaf(s_phi[jc], INVEPS, -(float)(u < 0 ? -u : u) * INVEPS);
            v = valid ? v : -3.0e38f;
            a[u + WIN] = v;
            m = fmaxf(m, v);
        }
        float s = 0.0f;
        #pragma unroll
        for (int u = 0; u < 2 * WIN + 1; u++) s += expf(a[u] - m);
        lse = m + logf(s);
        s_lse[j] = lse;
        __syncthreads();
        if (step == NSTEPS) break;
        // marginal_j over window, then phi update
        float mar = 0.0f;
        #pragma unroll
        for (int u = -WIN; u <= WIN; u++) {
            int i = j + u;
            bool valid = (i >= 0) && (i < KCB);
            int ic = valid ? i : j;
            float v = lt + fmaf(phi, INVEPS, -(float)(u < 0 ? -u : u) * INVEPS) - s_lse[ic];
            float c = s_src[ic] * expf(v);
            mar += valid ? c : 0.0f;
        }
        phi = phi + 0.5f * (tgt - mar);
        __syncthreads();
        s_phi[j] = phi;
        __syncthreads();
    }

    // ---- dual objective + loss ----
    float t1s = bsum(src * (-0.05f * lse), sh32, j);
    float t2s = bsum(tgt * phi, sh32, j);
    if (j == 0) {
        float obj = t1s + t2s;                        // ot_loss (OT_W = 1)
        float m = mse_tot / (float)QELEMS;            // codebook == commit value
        out[QELEMS] = (m + 0.25f * m) + obj;          // loss
    }
}

// ---------------- launch ----------------------------------------------------
extern "C" void kernel_launch(void* const* d_in, const int* in_sizes, int n_in,
                              void* d_out, int out_size) {
    const float* x  = (const float*)d_in[0];   // inputs [32,64,32,32]
    const float* cb = (const float*)d_in[1];   // codebook [1024,64]
    if (n_in >= 2 && in_sizes[0] == KCB * DIM && in_sizes[1] == QELEMS) {
        x = (const float*)d_in[1]; cb = (const float*)d_in[0];
    }
    float* out = (float*)d_out;

    k_sq<<<8, 128>>>(cb);
    k_main<<<NTOK / 128, 128>>>(x, cb, out);
    k_ot<<<1, 1024>>>(out);
}

// round 6
// speedup vs baseline: 2.0341x; 1.3546x over previous
#include <cuda_runtime.h>
#include <math.h>

// Problem constants
#define NTOK   32768      // B*H*W = 32*32*32
#define KCB    1024       // codebook entries
#define DIM    64         // embedding dim
#define HWSZ   1024       // H*W
#define QELEMS 2097152    // NTOK*DIM
#define INVEPS 20.0f      // 1/0.05
#define NSTEPS 10
#define NBLK   128        // k_main grid
#define TOKOFF 16384      // second token offset per thread
#define WIN    3          // OT stencil half-width; tail < e^-60 (validated R2)

// ---------------- scratch (device globals; all overwritten every launch) ----
__device__ int   g_idx[NTOK];
__device__ float g_msepart[NBLK];

// ---------------- K1: distances + argmin + quantized + mse -----------------
// 2 tokens per thread: each smem code load feeds 64 FMA2 (2 fp32 MACs each).
// Single wave: 128 blocks x 4 warps = 1 warp per SMSP on 128 SMs.
__global__ void __launch_bounds__(128, 1) k_main(const float* __restrict__ x,
                                                 const float* __restrict__ cb,
                                                 float* __restrict__ out) {
    const int tid = threadIdx.x;
    const int n0  = blockIdx.x * 128 + tid;
    const int n1  = n0 + TOKOFF;
    const int b0  = n0 >> 10, hw0 = n0 & 1023;
    const int b1  = n1 >> 10, hw1 = n1 & 1023;

    const float* xb0 = x + (size_t)b0 * (DIM * HWSZ) + hw0;
    const float* xb1 = x + (size_t)b1 * (DIM * HWSZ) + hw1;

    unsigned long long xp0[32], xp1[32];
    float xsq0 = 0.0f, xsq1 = 0.0f;
    #pragma unroll
    for (int t = 0; t < 32; t++) {
        float a0 = xb0[(2 * t) * HWSZ], a1 = xb0[(2 * t + 1) * HWSZ];
        float c0 = xb1[(2 * t) * HWSZ], c1 = xb1[(2 * t + 1) * HWSZ];
        xsq0 = fmaf(a0, a0, xsq0); xsq0 = fmaf(a1, a1, xsq0);
        xsq1 = fmaf(c0, c0, xsq1); xsq1 = fmaf(c1, c1, xsq1);
        asm("mov.b64 %0, {%1, %2};" : "=l"(xp0[t]) : "f"(a0), "f"(a1));
        asm("mov.b64 %0, {%1, %2};" : "=l"(xp1[t]) : "f"(c0), "f"(c1));
    }

    __shared__ float s_code[128 * DIM];   // 32 KB codebook chunk
    __shared__ float s_csq[128];

    float best0 = 3.4e38f, best1 = 3.4e38f;
    int   bj0 = 0, bj1 = 0;

    for (int c0i = 0; c0i < KCB; c0i += 128) {
        __syncthreads();
        const float4* src4 = (const float4*)(cb + (size_t)c0i * DIM);
        float4* dst4 = (float4*)s_code;
        #pragma unroll
        for (int t = 0; t < 16; t++) dst4[tid + 128 * t] = __ldg(src4 + tid + 128 * t);
        __syncthreads();
        // in-block |c|^2 for this chunk (row tid)
        {
            const float4* r = (const float4*)(s_code + tid * DIM);
            float s = 0.0f;
            #pragma unroll
            for (int t = 0; t < 16; t++) {
                float4 c = r[t];
                s = fmaf(c.x, c.x, s); s = fmaf(c.y, c.y, s);
                s = fmaf(c.z, c.z, s); s = fmaf(c.w, c.w, s);
            }
            s_csq[tid] = s;
        }
        __syncthreads();

        #pragma unroll 4
        for (int j = 0; j < 128; j++) {
            const ulonglong2* cp = (const ulonglong2*)(s_code + j * DIM);
            unsigned long long p0 = 0ull, p1 = 0ull, p2 = 0ull, p3 = 0ull;
            unsigned long long q0 = 0ull, q1 = 0ull, q2 = 0ull, q3 = 0ull;
            #pragma unroll
            for (int t = 0; t < 16; t += 2) {
                ulonglong2 cA = cp[t];
                ulonglong2 cB = cp[t + 1];
                asm("fma.rn.f32x2 %0, %1, %2, %0;" : "+l"(p0) : "l"(xp0[2 * t + 0]), "l"(cA.x));
                asm("fma.rn.f32x2 %0, %1, %2, %0;" : "+l"(q0) : "l"(xp1[2 * t + 0]), "l"(cA.x));
                asm("fma.rn.f32x2 %0, %1, %2, %0;" : "+l"(p1) : "l"(xp0[2 * t + 1]), "l"(cA.y));
                asm("fma.rn.f32x2 %0, %1, %2, %0;" : "+l"(q1) : "l"(xp1[2 * t + 1]), "l"(cA.y));
                asm("fma.rn.f32x2 %0, %1, %2, %0;" : "+l"(p2) : "l"(xp0[2 * t + 2]), "l"(cB.x));
                asm("fma.rn.f32x2 %0, %1, %2, %0;" : "+l"(q2) : "l"(xp1[2 * t + 2]), "l"(cB.x));
                asm("fma.rn.f32x2 %0, %1, %2, %0;" : "+l"(p3) : "l"(xp0[2 * t + 3]), "l"(cB.y));
                asm("fma.rn.f32x2 %0, %1, %2, %0;" : "+l"(q3) : "l"(xp1[2 * t + 3]), "l"(cB.y));
            }
            unsigned long long u01, u23, uu, v01, v23, vv;
            asm("add.rn.f32x2 %0, %1, %2;" : "=l"(u01) : "l"(p0), "l"(p1));
            asm("add.rn.f32x2 %0, %1, %2;" : "=l"(u23) : "l"(p2), "l"(p3));
            asm("add.rn.f32x2 %0, %1, %2;" : "=l"(uu)  : "l"(u01), "l"(u23));
            asm("add.rn.f32x2 %0, %1, %2;" : "=l"(v01) : "l"(q0), "l"(q1));
            asm("add.rn.f32x2 %0, %1, %2;" : "=l"(v23) : "l"(q2), "l"(q3));
            asm("add.rn.f32x2 %0, %1, %2;" : "=l"(vv)  : "l"(v01), "l"(v23));
            float lo0, hi0, lo1, hi1;
            asm("mov.b64 {%0, %1}, %2;" : "=f"(lo0), "=f"(hi0) : "l"(uu));
            asm("mov.b64 {%0, %1}, %2;" : "=f"(lo1), "=f"(hi1) : "l"(vv));
            float dot0 = lo0 + hi0;
            float dot1 = lo1 + hi1;
            float cs = s_csq[j];
            // faithful op structure: (|x|^2 + |c|^2) - 2*dot (no FMA contraction)
            float d0 = __fsub_rn(__fadd_rn(xsq0, cs), __fmul_rn(2.0f, dot0));
            float d1 = __fsub_rn(__fadd_rn(xsq1, cs), __fmul_rn(2.0f, dot1));
            if (d0 < best0) { best0 = d0; bj0 = c0i + j; }   // strict < = first-min
            if (d1 < best1) { best1 = d1; bj1 = c0i + j; }
        }
    }

    g_idx[n0] = bj0;
    g_idx[n1] = bj1;

    // quantized (straight-through value: x + (q - x)) + mse partials
    float ms = 0.0f;
    {
        const float4* q4 = (const float4*)(cb + (size_t)bj0 * DIM);
        float* ob = out + (size_t)b0 * (DIM * HWSZ) + hw0;
        #pragma unroll
        for (int t = 0; t < 16; t++) {
            float4 qv = __ldg(q4 + t);
            float x0, x1, x2, x3;
            asm("mov.b64 {%0, %1}, %2;" : "=f"(x0), "=f"(x1) : "l"(xp0[2 * t]));
            asm("mov.b64 {%0, %1}, %2;" : "=f"(x2), "=f"(x3) : "l"(xp0[2 * t + 1]));
            float d0 = __fsub_rn(qv.x, x0), d1 = __fsub_rn(qv.y, x1);
            float d2 = __fsub_rn(qv.z, x2), d3 = __fsub_rn(qv.w, x3);
            ms = fmaf(d0, d0, ms); ms = fmaf(d1, d1, ms);
            ms = fmaf(d2, d2, ms); ms = fmaf(d3, d3, ms);
            ob[(4 * t + 0) * HWSZ] = __fadd_rn(x0, d0);
            ob[(4 * t + 1) * HWSZ] = __fadd_rn(x1, d1);
            ob[(4 * t + 2) * HWSZ] = __fadd_rn(x2, d2);
            ob[(4 * t + 3) * HWSZ] = __fadd_rn(x3, d3);
        }
    }
    {
        const float4* q4 = (const float4*)(cb + (size_t)bj1 * DIM);
        float* ob = out + (size_t)b1 * (DIM * HWSZ) + hw1;
        #pragma unroll
        for (int t = 0; t < 16; t++) {
            float4 qv = __ldg(q4 + t);
            float x0, x1, x2, x3;
            asm("mov.b64 {%0, %1}, %2;" : "=f"(x0), "=f"(x1) : "l"(xp1[2 * t]));
            asm("mov.b64 {%0, %1}, %2;" : "=f"(x2), "=f"(x3) : "l"(xp1[2 * t + 1]));
            float d0 = __fsub_rn(qv.x, x0), d1 = __fsub_rn(qv.y, x1);
            float d2 = __fsub_rn(qv.z, x2), d3 = __fsub_rn(qv.w, x3);
            ms = fmaf(d0, d0, ms); ms = fmaf(d1, d1, ms);
            ms = fmaf(d2, d2, ms); ms = fmaf(d3, d3, ms);
            ob[(4 * t + 0) * HWSZ] = __fadd_rn(x0, d0);
            ob[(4 * t + 1) * HWSZ] = __fadd_rn(x1, d1);
            ob[(4 * t + 2) * HWSZ] = __fadd_rn(x2, d2);
            ob[(4 * t + 3) * HWSZ] = __fadd_rn(x3, d3);
        }
    }
    // deterministic per-block mse reduce
    #pragma unroll
    for (int o = 16; o > 0; o >>= 1) ms += __shfl_xor_sync(0xffffffffu, ms, o);
    __shared__ float s_ms[4];
    if ((tid & 31) == 0) s_ms[tid >> 5] = ms;
    __syncthreads();
    if (tid == 0) g_msepart[blockIdx.x] = (s_ms[0] + s_ms[1]) + (s_ms[2] + s_ms[3]);
}

// ---------------- block-wide sum (1024 threads) -----------------------------
__device__ __forceinline__ float bsum(float v, float* sh32, int tid) {
    #pragma unroll
    for (int o = 16; o > 0; o >>= 1) v += __shfl_xor_sync(0xffffffffu, v, o);
    if ((tid & 31) == 0) sh32[tid >> 5] = v;
    __syncthreads();
    if (tid < 32) {
        float w = sh32[tid];
        #pragma unroll
        for (int o = 16; o > 0; o >>= 1) w += __shfl_xor_sync(0xffffffffu, w, o);
        if (tid == 0) sh32[0] = w;
    }
    __syncthreads();
    float r = sh32[0];
    __syncthreads();
    return r;
}

// ---------------- K2: histogram + target + stats + OT dual + loss -----------
__global__ void __launch_bounds__(1024) k_ot(float* __restrict__ out) {
    const int j = threadIdx.x;
    __shared__ float sh32[32];
    __shared__ int   s_hist[KCB];
    __shared__ float s_lt[KCB];
    __shared__ float s_phi[KCB];
    __shared__ float s_lse[KCB];
    __shared__ float s_src[KCB];

    // ---- histogram from index array (integer atomics: deterministic) ----
    s_hist[j] = 0;
    __syncthreads();
    #pragma unroll
    for (int k = 0; k < 32; k++) {
        int idx = g_idx[j + KCB * k];
        atomicAdd(&s_hist[idx], 1);
    }
    __syncthreads();

    // ---- gaussian target (faithful: _gaussian_target then _norm_prob) ----
    float z = ((float)j - 511.5f) / (1024.0f / 6.0f);
    float t = expf(-0.5f * z * z);
    float sum1 = bsum(t, sh32, j);
    float t1 = t / fmaxf(sum1, 1e-12f);
    float t2 = fmaxf(t1, 1e-12f);
    float sum2 = bsum(t2, sh32, j);
    const float tgt = t2 / sum2;
    const float lt  = logf(fmaxf(tgt, 1e-12f));
    s_lt[j] = lt;

    // ---- perplexity ----
    float avg = (float)s_hist[j] / (float)NTOK;
    float ent = bsum(avg * logf(avg + 1e-10f), sh32, j);
    if (j == 0) out[QELEMS + 1] = expf(-ent);

    // ---- src weights: norm_prob(hard_hist) then norm_prob again ----
    float p1 = fmaxf(avg, 1e-12f);
    float s1 = bsum(p1, sh32, j);
    float p2 = fmaxf(p1 / s1, 1e-12f);
    float s2 = bsum(p2, sh32, j);
    const float src = p2 / s2;
    s_src[j] = src;

    // ---- total mse ----
    const float mse_tot = bsum((j < NBLK) ? g_msepart[j] : 0.0f, sh32, j);

    // ---- dual ascent loop (compile-time +/-WIN stencil, fully unrolled) ----
    float phi = 0.0f;
    s_phi[j] = 0.0f;
    __syncthreads();

    float lse = 0.0f;
    for (int step = 0; step <= NSTEPS; step++) {
        float a[2 * WIN + 1];
        float m = -3.4e38f;
        #pragma unroll
        for (int u = -WIN; u <= WIN; u++) {
            int jj = j + u;
            bool valid = (jj >= 0) && (jj < KCB);
            int jc = valid ? jj : j;
            float v = s_lt[jc] + fmaf(s_phi[jc], INVEPS, -(float)(u < 0 ? -u : u) * INVEPS);
            v = valid ? v : -3.0e38f;
            a[u + WIN] = v;
            m = fmaxf(m, v);
        }
        float s = 0.0f;
        #pragma unroll
        for (int u = 0; u < 2 * WIN + 1; u++) s += expf(a[u] - m);
        lse = m + logf(s);
        s_lse[j] = lse;
        __syncthreads();
        if (step == NSTEPS) break;
        float mar = 0.0f;
        #pragma unroll
        for (int u = -WIN; u <= WIN; u++) {
            int i = j + u;
            bool valid = (i >= 0) && (i < KCB);
            int ic = valid ? i : j;
            float v = lt + fmaf(phi, INVEPS, -(float)(u < 0 ? -u : u) * INVEPS) - s_lse[ic];
            float c = s_src[ic] * expf(v);
            mar += valid ? c : 0.0f;
        }
        phi = phi + 0.5f * (tgt - mar);
        __syncthreads();
        s_phi[j] = phi;
        __syncthreads();
    }

    // ---- dual objective + loss ----
    float t1s = bsum(src * (-0.05f * lse), sh32, j);
    float t2s = bsum(tgt * phi, sh32, j);
    if (j == 0) {
        float obj = t1s + t2s;                        // ot_loss (OT_W = 1)
        float m = mse_tot / (float)QELEMS;            // codebook == commit value
        out[QELEMS] = (m + 0.25f * m) + obj;          // loss
    }
}

// ---------------- launch ----------------------------------------------------
extern "C" void kernel_launch(void* const* d_in, const int* in_sizes, int n_in,
                              void* d_out, int out_size) {
    const float* x  = (const float*)d_in[0];   // inputs [32,64,32,32]
    const float* cb = (const float*)d_in[1];   // codebook [1024,64]
    if (n_in >= 2 && in_sizes[0] == KCB * DIM && in_sizes[1] == QELEMS) {
        x = (const float*)d_in[1]; cb = (const float*)d_in[0];
    }
    float* out = (float*)d_out;

    k_main<<<NBLK, 128>>>(x, cb, out);
    k_ot<<<1, 1024>>>(out);
}

// round 7
// speedup vs baseline: 2.1213x; 1.0429x over previous
#include <cuda_runtime.h>
#include <math.h>

// Problem constants
#define NTOK   32768      // B*H*W
#define KCB    1024
#define DIM    64
#define HWSZ   1024
#define QELEMS 2097152    // NTOK*DIM
#define INVEPS 20.0f
#define NSTEPS 10
#define NPAIR  128        // token groups (CTA pairs)
#define NFIN   256        // k_fin blocks / mse partials
#define TOKOFF 16384
#define WIN    3          // OT stencil half-width (validated: identical to exact)

// ---------------- scratch (device globals) ----------------------------------
__device__ float g_cd[2 * NTOK];      // candidate distance per half
__device__ int   g_ci[2 * NTOK];      // candidate index per half
__device__ int   g_hist[KCB];         // zero at module load; k_ot re-zeroes after use
__device__ float g_msepart[NFIN];

// ---------------- K1: split-K distances + argmin candidates -----------------
// 256 CTAs (2/SM, single wave, 2 warps/SMSP). CTA pair p: CTAs (2p, 2p+1)
// scan code halves [0,512) and [512,1024) for the same 256 tokens.
__global__ void __launch_bounds__(128, 2) k_main(const float* __restrict__ x,
                                                 const float* __restrict__ cb) {
    const int tid  = threadIdx.x;
    const int pair = blockIdx.x >> 1;
    const int half = blockIdx.x & 1;
    const int n0   = pair * 128 + tid;
    const int n1   = n0 + TOKOFF;
    const int b0   = n0 >> 10, hw0 = n0 & 1023;
    const int b1   = n1 >> 10, hw1 = n1 & 1023;

    const float* xb0 = x + (size_t)b0 * (DIM * HWSZ) + hw0;
    const float* xb1 = x + (size_t)b1 * (DIM * HWSZ) + hw1;

    unsigned long long xp0[32], xp1[32];
    float xsq0 = 0.0f, xsq1 = 0.0f;
    #pragma unroll
    for (int t = 0; t < 32; t++) {
        float a0 = xb0[(2 * t) * HWSZ], a1 = xb0[(2 * t + 1) * HWSZ];
        float c0 = xb1[(2 * t) * HWSZ], c1 = xb1[(2 * t + 1) * HWSZ];
        xsq0 = fmaf(a0, a0, xsq0); xsq0 = fmaf(a1, a1, xsq0);
        xsq1 = fmaf(c0, c0, xsq1); xsq1 = fmaf(c1, c1, xsq1);
        asm("mov.b64 %0, {%1, %2};" : "=l"(xp0[t]) : "f"(a0), "f"(a1));
        asm("mov.b64 %0, {%1, %2};" : "=l"(xp1[t]) : "f"(c0), "f"(c1));
    }

    __shared__ float s_code[128 * DIM];   // 32 KB chunk
    __shared__ float s_csq[128];

    float best0 = 3.4e38f, best1 = 3.4e38f;
    int   bj0 = half * 512, bj1 = half * 512;

    const int cbase = half * 512;
    for (int c0i = cbase; c0i < cbase + 512; c0i += 128) {
        __syncthreads();
        const float4* src4 = (const float4*)(cb + (size_t)c0i * DIM);
        float4* dst4 = (float4*)s_code;
        #pragma unroll
        for (int t = 0; t < 16; t++) dst4[tid + 128 * t] = __ldg(src4 + tid + 128 * t);
        __syncthreads();
        {   // in-block |c|^2 for row tid
            const float4* r = (const float4*)(s_code + tid * DIM);
            float s = 0.0f;
            #pragma unroll
            for (int t = 0; t < 16; t++) {
                float4 c = r[t];
                s = fmaf(c.x, c.x, s); s = fmaf(c.y, c.y, s);
                s = fmaf(c.z, c.z, s); s = fmaf(c.w, c.w, s);
            }
            s_csq[tid] = s;
        }
        __syncthreads();

        #pragma unroll 4
        for (int j = 0; j < 128; j++) {
            const ulonglong2* cp = (const ulonglong2*)(s_code + j * DIM);
            unsigned long long p0 = 0ull, p1 = 0ull, p2 = 0ull, p3 = 0ull;
            unsigned long long q0 = 0ull, q1 = 0ull, q2 = 0ull, q3 = 0ull;
            #pragma unroll
            for (int t = 0; t < 16; t += 2) {
                ulonglong2 cA = cp[t];
                ulonglong2 cB = cp[t + 1];
                asm("fma.rn.f32x2 %0, %1, %2, %0;" : "+l"(p0) : "l"(xp0[2 * t + 0]), "l"(cA.x));
                asm("fma.rn.f32x2 %0, %1, %2, %0;" : "+l"(q0) : "l"(xp1[2 * t + 0]), "l"(cA.x));
                asm("fma.rn.f32x2 %0, %1, %2, %0;" : "+l"(p1) : "l"(xp0[2 * t + 1]), "l"(cA.y));
                asm("fma.rn.f32x2 %0, %1, %2, %0;" : "+l"(q1) : "l"(xp1[2 * t + 1]), "l"(cA.y));
                asm("fma.rn.f32x2 %0, %1, %2, %0;" : "+l"(p2) : "l"(xp0[2 * t + 2]), "l"(cB.x));
                asm("fma.rn.f32x2 %0, %1, %2, %0;" : "+l"(q2) : "l"(xp1[2 * t + 2]), "l"(cB.x));
                asm("fma.rn.f32x2 %0, %1, %2, %0;" : "+l"(p3) : "l"(xp0[2 * t + 3]), "l"(cB.y));
                asm("fma.rn.f32x2 %0, %1, %2, %0;" : "+l"(q3) : "l"(xp1[2 * t + 3]), "l"(cB.y));
            }
            unsigned long long u01, u23, uu, v01, v23, vv;
            asm("add.rn.f32x2 %0, %1, %2;" : "=l"(u01) : "l"(p0), "l"(p1));
            asm("add.rn.f32x2 %0, %1, %2;" : "=l"(u23) : "l"(p2), "l"(p3));
            asm("add.rn.f32x2 %0, %1, %2;" : "=l"(uu)  : "l"(u01), "l"(u23));
            asm("add.rn.f32x2 %0, %1, %2;" : "=l"(v01) : "l"(q0), "l"(q1));
            asm("add.rn.f32x2 %0, %1, %2;" : "=l"(v23) : "l"(q2), "l"(q3));
            asm("add.rn.f32x2 %0, %1, %2;" : "=l"(vv)  : "l"(v01), "l"(v23));
            float lo0, hi0, lo1, hi1;
            asm("mov.b64 {%0, %1}, %2;" : "=f"(lo0), "=f"(hi0) : "l"(uu));
            asm("mov.b64 {%0, %1}, %2;" : "=f"(lo1), "=f"(hi1) : "l"(vv));
            float dot0 = lo0 + hi0;
            float dot1 = lo1 + hi1;
            float cs = s_csq[j];
            // faithful: (|x|^2 + |c|^2) - 2*dot, no FMA contraction
            float d0 = __fsub_rn(__fadd_rn(xsq0, cs), __fmul_rn(2.0f, dot0));
            float d1 = __fsub_rn(__fadd_rn(xsq1, cs), __fmul_rn(2.0f, dot1));
            if (d0 < best0) { best0 = d0; bj0 = c0i + j; }   // strict < = first-min
            if (d1 < best1) { best1 = d1; bj1 = c0i + j; }
        }
    }

    g_cd[half * NTOK + n0] = best0;  g_ci[half * NTOK + n0] = bj0;
    g_cd[half * NTOK + n1] = best1;  g_ci[half * NTOK + n1] = bj1;
}

// ---------------- K2: merge halves + quantized + mse + histogram ------------
__global__ void __launch_bounds__(128) k_fin(const float* __restrict__ x,
                                             const float* __restrict__ cb,
                                             float* __restrict__ out) {
    const int tid = threadIdx.x;
    const int n   = blockIdx.x * 128 + tid;
    const int b   = n >> 10, hw = n & 1023;

    __shared__ int s_hist[KCB];
    #pragma unroll
    for (int k = 0; k < 8; k++) s_hist[tid + 128 * k] = 0;

    // merge: lower half wins ties (first-min over full K)
    float dA = g_cd[n];
    float dB = g_cd[NTOK + n];
    int   iA = g_ci[n];
    int   iB = g_ci[NTOK + n];
    int bestj = (dB < dA) ? iB : iA;

    __syncthreads();
    atomicAdd(&s_hist[bestj], 1);

    // quantized output + mse
    const float* xb = x + (size_t)b * (DIM * HWSZ) + hw;
    const float4* q4 = (const float4*)(cb + (size_t)bestj * DIM);
    float* ob = out + (size_t)b * (DIM * HWSZ) + hw;
    float ms = 0.0f;
    #pragma unroll
    for (int t = 0; t < 16; t++) {
        float4 qv = __ldg(q4 + t);
        float x0 = xb[(4 * t + 0) * HWSZ];
        float x1 = xb[(4 * t + 1) * HWSZ];
        float x2 = xb[(4 * t + 2) * HWSZ];
        float x3 = xb[(4 * t + 3) * HWSZ];
        float d0 = __fsub_rn(qv.x, x0), d1 = __fsub_rn(qv.y, x1);
        float d2 = __fsub_rn(qv.z, x2), d3 = __fsub_rn(qv.w, x3);
        ms = fmaf(d0, d0, ms); ms = fmaf(d1, d1, ms);
        ms = fmaf(d2, d2, ms); ms = fmaf(d3, d3, ms);
        ob[(4 * t + 0) * HWSZ] = __fadd_rn(x0, d0);
        ob[(4 * t + 1) * HWSZ] = __fadd_rn(x1, d1);
        ob[(4 * t + 2) * HWSZ] = __fadd_rn(x2, d2);
        ob[(4 * t + 3) * HWSZ] = __fadd_rn(x3, d3);
    }
    #pragma unroll
    for (int o = 16; o > 0; o >>= 1) ms += __shfl_xor_sync(0xffffffffu, ms, o);
    __shared__ float s_ms[4];
    if ((tid & 31) == 0) s_ms[tid >> 5] = ms;
    __syncthreads();
    if (tid == 0) g_msepart[blockIdx.x] = (s_ms[0] + s_ms[1]) + (s_ms[2] + s_ms[3]);

    // sparse histogram flush (int atomics: deterministic)
    #pragma unroll
    for (int k = 0; k < 8; k++) {
        int v = s_hist[tid + 128 * k];
        if (v) atomicAdd(&g_hist[tid + 128 * k], v);
    }
}

// ---------------- block-wide sum (1024 threads) -----------------------------
__device__ __forceinline__ float bsum(float v, float* sh32, int tid) {
    #pragma unroll
    for (int o = 16; o > 0; o >>= 1) v += __shfl_xor_sync(0xffffffffu, v, o);
    if ((tid & 31) == 0) sh32[tid >> 5] = v;
    __syncthreads();
    if (tid < 32) {
        float w = sh32[tid];
        #pragma unroll
        for (int o = 16; o > 0; o >>= 1) w += __shfl_xor_sync(0xffffffffu, w, o);
        if (tid == 0) sh32[0] = w;
    }
    __syncthreads();
    float r = sh32[0];
    __syncthreads();
    return r;
}

// ---------------- K3: target + stats + OT dual + loss (one CTA) -------------
__global__ void __launch_bounds__(1024) k_ot(float* __restrict__ out) {
    const int j = threadIdx.x;
    __shared__ float sh32[32];
    __shared__ float s_lt[KCB];
    __shared__ float s_phi[KCB];
    __shared__ float s_lse[KCB];
    __shared__ float s_src[KCB];

    // consume histogram, then restore load-time-zero invariant for next replay
    const int hj = g_hist[j];
    g_hist[j] = 0;

    // gaussian target (faithful: _gaussian_target then _norm_prob)
    float z = ((float)j - 511.5f) / (1024.0f / 6.0f);
    float t = expf(-0.5f * z * z);
    float sum1 = bsum(t, sh32, j);
    float t1 = t / fmaxf(sum1, 1e-12f);
    float t2 = fmaxf(t1, 1e-12f);
    float sum2 = bsum(t2, sh32, j);
    const float tgt = t2 / sum2;
    const float lt  = logf(fmaxf(tgt, 1e-12f));
    s_lt[j] = lt;

    // perplexity
    float avg = (float)hj / (float)NTOK;
    float ent = bsum(avg * logf(avg + 1e-10f), sh32, j);
    if (j == 0) out[QELEMS + 1] = expf(-ent);

    // src weights: norm_prob(hard_hist), then norm_prob again (dual_obj)
    float p1 = fmaxf(avg, 1e-12f);
    float s1 = bsum(p1, sh32, j);
    float p2 = fmaxf(p1 / s1, 1e-12f);
    float s2 = bsum(p2, sh32, j);
    const float src = p2 / s2;
    s_src[j] = src;

    // total mse
    const float mse_tot = bsum((j < NFIN) ? g_msepart[j] : 0.0f, sh32, j);

    // dual ascent loop (compile-time +/-WIN stencil)
    float phi = 0.0f;
    s_phi[j] = 0.0f;
    __syncthreads();

    float lse = 0.0f;
    for (int step = 0; step <= NSTEPS; step++) {
        float a[2 * WIN + 1];
        float m = -3.4e38f;
        #pragma unroll
        for (int u = -WIN; u <= WIN; u++) {
            int jj = j + u;
            bool valid = (jj >= 0) && (jj < KCB);
            int jc = valid ? jj : j;
            float v = s_lt[jc] + fmaf(s_phi[jc], INVEPS, -(float)(u < 0 ? -u : u) * INVEPS);
            v = valid ? v : -3.0e38f;
            a[u + WIN] = v;
            m = fmaxf(m, v);
        }
        float s = 0.0f;
        #pragma unroll
        for (int u = 0; u < 2 * WIN + 1; u++) s += expf(a[u] - m);
        lse = m + logf(s);
        s_lse[j] = lse;
        __syncthreads();
        if (step == NSTEPS) break;
        float mar = 0.0f;
        #pragma unroll
        for (int u = -WIN; u <= WIN; u++) {
            int i = j + u;
            bool valid = (i >= 0) && (i < KCB);
            int ic = valid ? i : j;
            float v = lt + fmaf(phi, INVEPS, -(float)(u < 0 ? -u : u) * INVEPS) - s_lse[ic];
            float c = s_src[ic] * expf(v);
            mar += valid ? c : 0.0f;
        }
        phi = phi + 0.5f * (tgt - mar);
        __syncthreads();
        s_phi[j] = phi;
        __syncthreads();
    }

    // dual objective + loss
    float t1s = bsum(src * (-0.05f * lse), sh32, j);
    float t2s = bsum(tgt * phi, sh32, j);
    if (j == 0) {
        float obj = t1s + t2s;                        // ot_loss (OT_W = 1)
        float m = mse_tot / (float)QELEMS;            // codebook == commit value
        out[QELEMS] = (m + 0.25f * m) + obj;          // loss
    }
}

// ---------------- launch ----------------------------------------------------
extern "C" void kernel_launch(void* const* d_in, const int* in_sizes, int n_in,
                              void* d_out, int out_size) {
    const float* x  = (const float*)d_in[0];   // inputs [32,64,32,32]
    const float* cb = (const float*)d_in[1];   // codebook [1024,64]
    if (n_in >= 2 && in_sizes[0] == KCB * DIM && in_sizes[1] == QELEMS) {
        x = (const float*)d_in[1]; cb = (const float*)d_in[0];
    }
    float* out = (float*)d_out;

    k_main<<<2 * NPAIR, 128>>>(x, cb);
    k_fin<<<NFIN, 128>>>(x, cb, out);
    k_ot<<<1, 1024>>>(out);
}